// round 2
// baseline (speedup 1.0000x reference)
#include <cuda_runtime.h>
#include <cuda_bf16.h>

#define N_NODES 100000
#define N_EDGES 1600000

// Scratch (allocations are forbidden; device globals are the sanctioned escape hatch)
__device__ float g_bufA[N_NODES * 64];   // support buffer
__device__ float g_bufB[N_NODES * 64];   // h buffer
__device__ float g_pool[64];

// ---------------------------------------------------------------------------
// Tiled GEMM: out[n*F+f] = sum_k act(X[n*K+k]) * W[k*F+f]
// Block: 256 threads, 64-node tile. Each thread: 2 nodes x (F/8) cols.
// ---------------------------------------------------------------------------
template <int K, int F, bool RELU>
__global__ void __launch_bounds__(256)
gemm_kernel(const float* __restrict__ X, const float* __restrict__ W,
            float* __restrict__ out) {
    constexpr int NODE_TILE = 64;
    constexpr int KC  = (K >= 64) ? 32 : K;       // K-chunk staged in smem
    constexpr int NCH = K / KC;
    constexpr int WS  = (F == 64) ? 65 : F;       // pad to kill 2-way bank conflicts
    constexpr int FT  = F / 8;                    // cols per thread

    __shared__ float Ws[K * WS];
    __shared__ float xs[NODE_TILE * KC];

    const int tid = threadIdx.x;

    // Stage full W into smem (padded stride)
    for (int i = tid; i < K * F; i += 256) {
        int k = i / F, f = i % F;
        Ws[k * WS + f] = W[i];
    }

    const int node0  = blockIdx.x * NODE_TILE;
    const int fgroup = tid & 7;     // 0..7
    const int ngroup = tid >> 3;    // 0..31

    float acc[2][FT];
#pragma unroll
    for (int a = 0; a < 2; a++)
#pragma unroll
        for (int b = 0; b < FT; b++) acc[a][b] = 0.f;

    for (int ch = 0; ch < NCH; ch++) {
        const int kc = ch * KC;
        __syncthreads();   // protects Ws (first iter) and xs reuse (later iters)
        for (int i = tid; i < NODE_TILE * KC; i += 256) {
            int n = i / KC, k = i % KC;
            int gn = node0 + n;
            float v = 0.f;
            if (gn < N_NODES) {
                v = X[gn * K + kc + k];
                if (RELU) v = fmaxf(v, 0.f);
            }
            xs[n * KC + k] = v;
        }
        __syncthreads();

#pragma unroll 4
        for (int k = 0; k < KC; k++) {
            float x0 = xs[(ngroup * 2 + 0) * KC + k];
            float x1 = xs[(ngroup * 2 + 1) * KC + k];
#pragma unroll
            for (int fi = 0; fi < FT; fi++) {
                float w = Ws[(kc + k) * WS + fgroup * FT + fi];
                acc[0][fi] += x0 * w;
                acc[1][fi] += x1 * w;
            }
        }
    }

#pragma unroll
    for (int ni = 0; ni < 2; ni++) {
        int gn = node0 + ngroup * 2 + ni;
        if (gn < N_NODES) {
#pragma unroll
            for (int fi = 0; fi < FT; fi++)
                out[gn * F + fgroup * FT + fi] = acc[ni][fi];
        }
    }
}

// ---------------------------------------------------------------------------
// out[n*F + f] = b[f]   (bias init; SPMM accumulates on top). float4 path.
// F is a multiple of 4, so each float4 covers cols [4c, 4c+4) with c = (i % (F/4)).
// ---------------------------------------------------------------------------
template <int F>
__global__ void __launch_bounds__(256)
init_bias_kernel(float4* __restrict__ out, const float* __restrict__ b) {
    constexpr int Q = F / 4;
    int i = blockIdx.x * blockDim.x + threadIdx.x;
    if (i >= N_NODES * Q) return;
    int c = i % Q;
    float4 v = reinterpret_cast<const float4*>(b)[c];
    out[i] = v;
}

// ---------------------------------------------------------------------------
// SPMM: for each edge e: out[row[e]] += val[e] * sup[col[e]]
// F/4 lanes per edge, float4 gather + vector red.global.add.v4.f32 scatter.
// ---------------------------------------------------------------------------
template <int F>
__global__ void __launch_bounds__(256)
spmm_kernel(const int* __restrict__ row, const int* __restrict__ col,
            const float* __restrict__ val, const float* __restrict__ sup,
            float* __restrict__ out) {
    constexpr int LPE = F / 4;  // lanes per edge
    long long idx = (long long)blockIdx.x * blockDim.x + threadIdx.x;
    int e = (int)(idx / LPE);
    int p = (int)(idx % LPE);
    if (e >= N_EDGES) return;

    int r = row[e];
    int c = col[e];
    float v = val[e];

    const float4* s4 = reinterpret_cast<const float4*>(sup + (size_t)c * F);
    float4 s = __ldg(&s4[p]);

    float* dst = out + (size_t)r * F + p * 4;
    asm volatile("red.global.add.v4.f32 [%0], {%1,%2,%3,%4};"
                 :: "l"(dst), "f"(s.x * v), "f"(s.y * v), "f"(s.z * v), "f"(s.w * v)
                 : "memory");
}

// ---------------------------------------------------------------------------
// Mean pool over relu(h3): g_pool[f] = sum_n relu(h[n*64+f])
// ---------------------------------------------------------------------------
__global__ void zero_pool_kernel() {
    if (threadIdx.x < 64) g_pool[threadIdx.x] = 0.f;
}

__global__ void __launch_bounds__(256)
pool_kernel(const float* __restrict__ h) {
    int colf = threadIdx.x & 63;
    int r0 = blockIdx.x * 4 + (threadIdx.x >> 6);
    float s = 0.f;
    for (int n = r0; n < N_NODES; n += gridDim.x * 4)
        s += fmaxf(h[n * 64 + colf], 0.f);
    atomicAdd(&g_pool[colf], s);
}

// ---------------------------------------------------------------------------
// Head: y = mean; relu(y @ fc1 + b); softmax(z @ fc2 + b). One block.
// ---------------------------------------------------------------------------
__global__ void head_kernel(const float* __restrict__ fc1_W, const float* __restrict__ fc1_b,
                            const float* __restrict__ fc2_W, const float* __restrict__ fc2_b,
                            float* __restrict__ out) {
    __shared__ float y64[64];
    __shared__ float z32[32];
    int t = threadIdx.x;
    if (t < 64) y64[t] = g_pool[t] * (1.0f / N_NODES);
    __syncthreads();
    if (t < 32) {
        float a = fc1_b[t];
#pragma unroll
        for (int j = 0; j < 64; j++) a += y64[j] * fc1_W[j * 32 + t];
        z32[t] = fmaxf(a, 0.f);
    }
    __syncthreads();
    if (t == 0) {
        float l0 = fc2_b[0], l1 = fc2_b[1];
#pragma unroll
        for (int i = 0; i < 32; i++) {
            l0 += z32[i] * fc2_W[i * 2 + 0];
            l1 += z32[i] * fc2_W[i * 2 + 1];
        }
        float m  = fmaxf(l0, l1);
        float e0 = expf(l0 - m), e1 = expf(l1 - m);
        float inv = 1.0f / (e0 + e1);
        out[0] = e0 * inv;
        out[1] = e1 * inv;
    }
}

// ---------------------------------------------------------------------------
extern "C" void kernel_launch(void* const* d_in, const int* in_sizes, int n_in,
                              void* d_out, int out_size) {
    const float* x    = (const float*)d_in[0];
    const int*   row  = (const int*)  d_in[1];
    const int*   col  = (const int*)  d_in[2];
    const float* ev   = (const float*)d_in[3];
    const float* W1   = (const float*)d_in[4];
    const float* b1   = (const float*)d_in[5];
    const float* W2   = (const float*)d_in[6];
    const float* b2   = (const float*)d_in[7];
    const float* W3   = (const float*)d_in[8];
    const float* b3   = (const float*)d_in[9];
    const float* f1W  = (const float*)d_in[10];
    const float* f1b  = (const float*)d_in[11];
    const float* f2W  = (const float*)d_in[12];
    const float* f2b  = (const float*)d_in[13];
    float* out = (float*)d_out;

    float *A, *B;
    cudaGetSymbolAddress((void**)&A, g_bufA);
    cudaGetSymbolAddress((void**)&B, g_bufB);

    const int GB = (N_NODES + 63) / 64;  // gemm blocks

    // Layer 1: A = x @ W1 ; B = b1 ; B += spmm(A)
    gemm_kernel<256, 32, false><<<GB, 256>>>(x, W1, A);
    init_bias_kernel<32><<<(N_NODES * 8 + 255) / 256, 256>>>((float4*)B, b1);
    spmm_kernel<32><<<(int)((N_EDGES * 8LL + 255) / 256), 256>>>(row, col, ev, A, B);

    // Layer 2: A = relu(B) @ W2 ; B = b2 ; B += spmm(A)
    gemm_kernel<32, 48, true><<<GB, 256>>>(B, W2, A);
    init_bias_kernel<48><<<(N_NODES * 12 + 255) / 256, 256>>>((float4*)B, b2);
    spmm_kernel<48><<<(int)((N_EDGES * 12LL + 255) / 256), 256>>>(row, col, ev, A, B);

    // Layer 3: A = relu(B) @ W3 ; B = b3 ; B += spmm(A)
    gemm_kernel<48, 64, true><<<GB, 256>>>(B, W3, A);
    init_bias_kernel<64><<<(N_NODES * 16 + 255) / 256, 256>>>((float4*)B, b3);
    spmm_kernel<64><<<(int)((N_EDGES * 16LL + 255) / 256), 256>>>(row, col, ev, A, B);

    // Pool + head
    zero_pool_kernel<<<1, 64>>>();
    pool_kernel<<<1184, 256>>>(B);
    head_kernel<<<1, 64>>>(f1W, f1b, f2W, f2b, out);
}

// round 3
// speedup vs baseline: 1.3047x; 1.3047x over previous
#include <cuda_runtime.h>
#include <cuda_bf16.h>

#define N_NODES 100000
#define N_EDGES 1600000

#define SCAN_CHUNK 512
#define SCAN_NB ((N_NODES + SCAN_CHUNK - 1) / SCAN_CHUNK)   // 196

// Scratch (allocations forbidden; device globals are the sanctioned escape hatch)
__device__ float g_bufA[N_NODES * 64];     // support buffer
__device__ float g_bufB[N_NODES * 64];     // h buffer
__device__ float g_pool[64];

__device__ int   g_rowptr[N_NODES + 1];
__device__ int   g_cnt[N_NODES];
__device__ int   g_blocksum[256];
__device__ int   g_csr_col[N_EDGES];
__device__ float g_csr_val[N_EDGES];

// ===========================================================================
// CSR build: histogram -> chunked exclusive scan -> scatter
// ===========================================================================
__global__ void zero_cnt_kernel() {
    int i = blockIdx.x * blockDim.x + threadIdx.x;
    if (i < N_NODES) g_cnt[i] = 0;
}

__global__ void hist_kernel(const int* __restrict__ row) {
    int e = blockIdx.x * blockDim.x + threadIdx.x;
    if (e < N_EDGES) atomicAdd(&g_cnt[row[e]], 1);
}

__global__ void __launch_bounds__(SCAN_CHUNK)
chunk_sum_kernel() {
    __shared__ int s[SCAN_CHUNK];
    int t = threadIdx.x;
    int i = blockIdx.x * SCAN_CHUNK + t;
    s[t] = (i < N_NODES) ? g_cnt[i] : 0;
    __syncthreads();
    for (int off = SCAN_CHUNK / 2; off > 0; off >>= 1) {
        if (t < off) s[t] += s[t + off];
        __syncthreads();
    }
    if (t == 0) g_blocksum[blockIdx.x] = s[0];
}

__global__ void scan_blocksum_kernel() {
    if (threadIdx.x == 0) {
        int acc = 0;
        for (int b = 0; b < SCAN_NB; b++) {
            int v = g_blocksum[b];
            g_blocksum[b] = acc;
            acc += v;
        }
        g_rowptr[N_NODES] = N_EDGES;
    }
}

__global__ void __launch_bounds__(SCAN_CHUNK)
chunk_scan_kernel() {
    __shared__ int s[SCAN_CHUNK];
    int t = threadIdx.x;
    int i = blockIdx.x * SCAN_CHUNK + t;
    int v = (i < N_NODES) ? g_cnt[i] : 0;
    s[t] = v;
    __syncthreads();
    // Hillis-Steele inclusive scan
    for (int off = 1; off < SCAN_CHUNK; off <<= 1) {
        int add = (t >= off) ? s[t - off] : 0;
        __syncthreads();
        s[t] += add;
        __syncthreads();
    }
    if (i < N_NODES) g_rowptr[i] = g_blocksum[blockIdx.x] + (s[t] - v);  // exclusive
}

__global__ void scatter_kernel(const int* __restrict__ row, const int* __restrict__ col,
                               const float* __restrict__ val) {
    int e = blockIdx.x * blockDim.x + threadIdx.x;
    if (e >= N_EDGES) return;
    int r = row[e];
    int p = g_rowptr[r] + atomicAdd(&g_cnt[r], 1);
    g_csr_col[p] = col[e];
    g_csr_val[p] = val[e];
}

// ===========================================================================
// Tiled GEMM: out[n*F+f] = sum_k act(X[n*K+k]) * W[k*F+f]
// 256 threads, 128-node tile, 4 nodes x (F/8) cols per thread.
// ===========================================================================
template <int K, int F, bool RELU>
__global__ void __launch_bounds__(256)
gemm_kernel(const float* __restrict__ X, const float* __restrict__ W,
            float* __restrict__ out) {
    constexpr int NT  = 128;                      // node tile
    constexpr int KC  = (K >= 64) ? 32 : K;       // K-chunk staged in smem
    constexpr int NCH = K / KC;
    constexpr int WS  = F;                        // W smem row stride
    constexpr int FT  = F / 8;                    // cols per thread
    constexpr int KQ  = KC / 4;

    __shared__ float Ws[KC * WS];
    __shared__ float xs[NT * KC];

    const int tid    = threadIdx.x;
    const int node0  = blockIdx.x * NT;
    const int fgroup = tid & 7;     // 0..7
    const int ngroup = tid >> 3;    // 0..31

    float acc[4][FT];
#pragma unroll
    for (int a = 0; a < 4; a++)
#pragma unroll
        for (int b = 0; b < FT; b++) acc[a][b] = 0.f;

    for (int ch = 0; ch < NCH; ch++) {
        const int kc = ch * KC;
        __syncthreads();
        // stage W chunk
        for (int i = tid; i < KC * F; i += 256) {
            int k = i / F, f = i % F;
            Ws[k * WS + f] = W[(kc + k) * F + f];
        }
        // stage X tile (float4, relu fused)
        for (int i = tid; i < NT * KQ; i += 256) {
            int n = i / KQ, kq = i % KQ;
            int gn = node0 + n;
            float4 v = make_float4(0.f, 0.f, 0.f, 0.f);
            if (gn < N_NODES) {
                v = reinterpret_cast<const float4*>(X + (size_t)gn * K + kc)[kq];
                if (RELU) {
                    v.x = fmaxf(v.x, 0.f); v.y = fmaxf(v.y, 0.f);
                    v.z = fmaxf(v.z, 0.f); v.w = fmaxf(v.w, 0.f);
                }
            }
            reinterpret_cast<float4*>(xs)[i] = v;  // xs[n*KC + kq*4 ..]
        }
        __syncthreads();

#pragma unroll 4
        for (int k = 0; k < KC; k++) {
            float x0 = xs[(ngroup * 4 + 0) * KC + k];
            float x1 = xs[(ngroup * 4 + 1) * KC + k];
            float x2 = xs[(ngroup * 4 + 2) * KC + k];
            float x3 = xs[(ngroup * 4 + 3) * KC + k];
#pragma unroll
            for (int fi = 0; fi < FT; fi++) {
                float w = Ws[k * WS + fgroup * FT + fi];
                acc[0][fi] += x0 * w;
                acc[1][fi] += x1 * w;
                acc[2][fi] += x2 * w;
                acc[3][fi] += x3 * w;
            }
        }
    }

#pragma unroll
    for (int ni = 0; ni < 4; ni++) {
        int gn = node0 + ngroup * 4 + ni;
        if (gn < N_NODES) {
            float* dst = out + (size_t)gn * F + fgroup * FT;
            if constexpr (FT % 4 == 0) {
#pragma unroll
                for (int q = 0; q < FT / 4; q++)
                    reinterpret_cast<float4*>(dst)[q] =
                        make_float4(acc[ni][q*4+0], acc[ni][q*4+1], acc[ni][q*4+2], acc[ni][q*4+3]);
            } else {
#pragma unroll
                for (int fi = 0; fi < FT; fi++) dst[fi] = acc[ni][fi];
            }
        }
    }
}

// ===========================================================================
// CSR SPMM with fused bias: out[n] = bias + sum_j val[j] * sup[col[j]]
// Group of F/4 threads per node; each thread owns one float4 feature chunk.
// ===========================================================================
template <int F>
__global__ void __launch_bounds__(256)
spmm_csr_kernel(const float* __restrict__ sup, const float* __restrict__ bias,
                float* __restrict__ out) {
    constexpr int G = F / 4;
    int idx = blockIdx.x * blockDim.x + threadIdx.x;
    int n = idx / G;
    int p = idx % G;
    if (n >= N_NODES) return;

    float4 acc = reinterpret_cast<const float4*>(bias)[p];
    const float4* s4 = reinterpret_cast<const float4*>(sup);

    int j   = g_rowptr[n];
    int end = g_rowptr[n + 1];

    for (; j + 4 <= end; j += 4) {
        int   c0 = g_csr_col[j],     c1 = g_csr_col[j + 1];
        int   c2 = g_csr_col[j + 2], c3 = g_csr_col[j + 3];
        float v0 = g_csr_val[j],     v1 = g_csr_val[j + 1];
        float v2 = g_csr_val[j + 2], v3 = g_csr_val[j + 3];
        float4 a = __ldg(&s4[c0 * G + p]);
        float4 b = __ldg(&s4[c1 * G + p]);
        float4 c = __ldg(&s4[c2 * G + p]);
        float4 d = __ldg(&s4[c3 * G + p]);
        acc.x += v0 * a.x + v1 * b.x + v2 * c.x + v3 * d.x;
        acc.y += v0 * a.y + v1 * b.y + v2 * c.y + v3 * d.y;
        acc.z += v0 * a.z + v1 * b.z + v2 * c.z + v3 * d.z;
        acc.w += v0 * a.w + v1 * b.w + v2 * c.w + v3 * d.w;
    }
    for (; j < end; j++) {
        int   c = g_csr_col[j];
        float v = g_csr_val[j];
        float4 a = __ldg(&s4[c * G + p]);
        acc.x += v * a.x; acc.y += v * a.y; acc.z += v * a.z; acc.w += v * a.w;
    }
    reinterpret_cast<float4*>(out)[n * G + p] = acc;
}

// ===========================================================================
// Mean pool over relu(h3)
// ===========================================================================
__global__ void zero_pool_kernel() {
    if (threadIdx.x < 64) g_pool[threadIdx.x] = 0.f;
}

__global__ void __launch_bounds__(256)
pool_kernel(const float* __restrict__ h) {
    int colf = threadIdx.x & 63;
    int r0 = blockIdx.x * 4 + (threadIdx.x >> 6);
    float s = 0.f;
    for (int n = r0; n < N_NODES; n += gridDim.x * 4)
        s += fmaxf(h[n * 64 + colf], 0.f);
    atomicAdd(&g_pool[colf], s);
}

// ===========================================================================
// Head: y = mean; relu(y @ fc1 + b); softmax(z @ fc2 + b). One block.
// ===========================================================================
__global__ void head_kernel(const float* __restrict__ fc1_W, const float* __restrict__ fc1_b,
                            const float* __restrict__ fc2_W, const float* __restrict__ fc2_b,
                            float* __restrict__ out) {
    __shared__ float y64[64];
    __shared__ float z32[32];
    int t = threadIdx.x;
    if (t < 64) y64[t] = g_pool[t] * (1.0f / N_NODES);
    __syncthreads();
    if (t < 32) {
        float a = fc1_b[t];
#pragma unroll
        for (int j = 0; j < 64; j++) a += y64[j] * fc1_W[j * 32 + t];
        z32[t] = fmaxf(a, 0.f);
    }
    __syncthreads();
    if (t == 0) {
        float l0 = fc2_b[0], l1 = fc2_b[1];
#pragma unroll
        for (int i = 0; i < 32; i++) {
            l0 += z32[i] * fc2_W[i * 2 + 0];
            l1 += z32[i] * fc2_W[i * 2 + 1];
        }
        float m  = fmaxf(l0, l1);
        float e0 = expf(l0 - m), e1 = expf(l1 - m);
        float inv = 1.0f / (e0 + e1);
        out[0] = e0 * inv;
        out[1] = e1 * inv;
    }
}

// ===========================================================================
extern "C" void kernel_launch(void* const* d_in, const int* in_sizes, int n_in,
                              void* d_out, int out_size) {
    const float* x    = (const float*)d_in[0];
    const int*   row  = (const int*)  d_in[1];
    const int*   col  = (const int*)  d_in[2];
    const float* ev   = (const float*)d_in[3];
    const float* W1   = (const float*)d_in[4];
    const float* b1   = (const float*)d_in[5];
    const float* W2   = (const float*)d_in[6];
    const float* b2   = (const float*)d_in[7];
    const float* W3   = (const float*)d_in[8];
    const float* b3   = (const float*)d_in[9];
    const float* f1W  = (const float*)d_in[10];
    const float* f1b  = (const float*)d_in[11];
    const float* f2W  = (const float*)d_in[12];
    const float* f2b  = (const float*)d_in[13];
    float* out = (float*)d_out;

    float *A, *B;
    cudaGetSymbolAddress((void**)&A, g_bufA);
    cudaGetSymbolAddress((void**)&B, g_bufB);

    const int GB = (N_NODES + 127) / 128;   // gemm blocks (128-node tiles)
    const int EB = (N_EDGES + 255) / 256;   // edge-parallel blocks
    const int NB = (N_NODES + 255) / 256;

    // ---- CSR build (reused by all 3 layers) ----
    zero_cnt_kernel<<<NB, 256>>>();
    hist_kernel<<<EB, 256>>>(row);
    chunk_sum_kernel<<<SCAN_NB, SCAN_CHUNK>>>();
    scan_blocksum_kernel<<<1, 32>>>();
    chunk_scan_kernel<<<SCAN_NB, SCAN_CHUNK>>>();
    zero_cnt_kernel<<<NB, 256>>>();
    scatter_kernel<<<EB, 256>>>(row, col, ev);

    // ---- Layer 1: A = x @ W1 ; B = bias + spmm(A) ----
    gemm_kernel<256, 32, false><<<GB, 256>>>(x, W1, A);
    spmm_csr_kernel<32><<<(N_NODES * 8 + 255) / 256, 256>>>(A, b1, B);

    // ---- Layer 2: A = relu(B) @ W2 ; B = bias + spmm(A) ----
    gemm_kernel<32, 48, true><<<GB, 256>>>(B, W2, A);
    spmm_csr_kernel<48><<<(N_NODES * 12 + 255) / 256, 256>>>(A, b2, B);

    // ---- Layer 3: A = relu(B) @ W3 ; B = bias + spmm(A) ----
    gemm_kernel<48, 64, true><<<GB, 256>>>(B, W3, A);
    spmm_csr_kernel<64><<<(N_NODES * 16 + 255) / 256, 256>>>(A, b3, B);

    // ---- Pool + head ----
    zero_pool_kernel<<<1, 64>>>();
    pool_kernel<<<1184, 256>>>(B);
    head_kernel<<<1, 64>>>(f1W, f1b, f2W, f2b, out);
}